// round 8
// baseline (speedup 1.0000x reference)
#include <cuda_runtime.h>
#include <cuda_fp16.h>

#define NROWS 16384
#define NCOL  1024
#define NPAIR (NROWS / 2)     /* 8192 row pairs; each CTA iter covers 2 rows */
#define NTHR  256
#define GRID  592             /* 148 SMs x 4 CTAs, persistent */
#define NIT   20
#define CSS   64              /* colsum counter stride in floats (256 B) */
#define THR   0.05f           /* ALPHA*LAMBD/RHO */
#define SHRK  0.05f           /* (1-ALPHA)*LAMBD */
#define EPSI  1e-10f
#define SQMIN 1e-20f          /* sqrt(MIN_VALUE) */
#define K2E   (-0.72134752044448170f)  /* -0.5 * log2(e) */

__device__ __half g_u[NROWS * NCOL];                 /* fp16 u_k = R_k + Z_{k-1}; u > 0 always */
__device__ __half g_h[NROWS * NCOL];                 /* fp16 sqrt(R_0c) */
__device__ float  g_cs[(size_t)NIT * NCOL * CSS];

__global__ void k_zero() {
    g_cs[((size_t)blockIdx.x * NCOL + threadIdx.x) * CSS] = 0.0f;
}

__device__ __forceinline__ float ex2(float x) {
    float r;
    asm("ex2.approx.f32 %0, %1;" : "=f"(r) : "f"(x));
    return r;
}

__device__ __forceinline__ float wredsum(float v) {
#pragma unroll
    for (int o = 16; o > 0; o >>= 1) v += __shfl_xor_sync(0xffffffffu, v, o);
    return v;
}

__device__ __forceinline__ void cvt8(const uint4 pk, float f[8]) {
    const __half2* h = reinterpret_cast<const __half2*>(&pk);
#pragma unroll
    for (int i = 0; i < 4; ++i) {
        float2 t = __half22float2(h[i]);
        f[2 * i] = t.x; f[2 * i + 1] = t.y;
    }
}

__device__ __forceinline__ void st8h(__half* p, const float f[8]) {
    uint4 pk;
    __half2* h = reinterpret_cast<__half2*>(&pk);
#pragma unroll
    for (int i = 0; i < 4; ++i) h[i] = __floats2half2_rn(f[2 * i], f[2 * i + 1]);
    *(uint4*)p = pk;
}

// u_1 = R_1 = R_0c / rowsum(R_0c)  (Z_0 = 0); writes fp16 u_1, fp16 sqrt(R_0c); colsum_1.
// Layout: 128 threads per row (4 warps), 8 cols per thread; CTA covers 2 rows per iter.
__global__ void __launch_bounds__(NTHR, 4) k_init(const float* __restrict__ r0) {
    __shared__ float sp[2][2][4];
    const int tid  = threadIdx.x;
    const int half = tid >> 7;          /* which of the 2 rows */
    const int ctid = tid & 127;
    const int lane = tid & 31;
    const int wir  = ctid >> 5;         /* warp index within row: 0..3 */
    const int col  = ctid * 8;

    float c8[8] = {0.f, 0.f, 0.f, 0.f, 0.f, 0.f, 0.f, 0.f};

    float4 a0, a1;
    {
        const size_t b = ((size_t)(blockIdx.x * 2 + half)) * NCOL + col;
        a0 = *(const float4*)(r0 + b);
        a1 = *(const float4*)(r0 + b + 4);
    }

    int it = 0;
    for (int w = blockIdx.x; w < NPAIR; w += GRID, ++it) {
        const int cur = it & 1;
        float v[8] = {a0.x, a0.y, a0.z, a0.w, a1.x, a1.y, a1.z, a1.w};
#pragma unroll
        for (int j = 0; j < 8; ++j)
            if (v[j] == 0.0f) v[j] = 1e-40f;

        float local = ((v[0] + v[1]) + (v[2] + v[3])) + ((v[4] + v[5]) + (v[6] + v[7]));
        local = wredsum(local);
        if (lane == 0) sp[cur][half][wir] = local;

        int nw = w + GRID; if (nw >= NPAIR) nw = w;     /* safe redundant prefetch */
        {
            const size_t nb = ((size_t)(nw * 2 + half)) * NCOL + col;
            a0 = *(const float4*)(r0 + nb);
            a1 = *(const float4*)(r0 + nb + 4);
        }
        __syncthreads();
        const float S = (sp[cur][half][0] + sp[cur][half][1]) +
                        (sp[cur][half][2] + sp[cur][half][3]);
        const float inv = __fdividef(1.0f, S);

        const size_t base = ((size_t)(w * 2 + half)) * NCOL + col;
        float rn[8], q[8];
#pragma unroll
        for (int j = 0; j < 8; ++j) { rn[j] = v[j] * inv; q[j] = sqrtf(v[j]); }
        st8h(g_u + base, rn);
        st8h(g_h + base, q);
#pragma unroll
        for (int j = 0; j < 8; ++j) {
            float s = fmaxf(rn[j] - THR, 0.0f);
            c8[j] += s * s;
        }
    }
#pragma unroll
    for (int j = 0; j < 8; ++j)
        atomicAdd(&g_cs[((size_t)1 * NCOL + col + j) * CSS], c8[j]);
}

// Step k: u_k -> u_{k+1}, colsum_{k+1}; last step writes fp32 R_20 to out.
// e = sqrt(r0c) * (sqrt(X) + 1e-20) * exp(-z/2)
//   (X==0 -> exactly the reference MIN_VALUE branch; X>0 -> 1e-19 relative noise)
__global__ void __launch_bounds__(NTHR, 4) k_step(float* __restrict__ out,
                                                  int k, int rev, int last) {
    __shared__ float sp[2][2][4];
    const int tid  = threadIdx.x;
    const int half = tid >> 7;
    const int ctid = tid & 127;
    const int lane = tid & 31;
    const int wir  = ctid >> 5;
    const int col  = ctid * 8;

    float sc[8];
#pragma unroll
    for (int j = 0; j < 8; ++j) {
        float cs = g_cs[((size_t)k * NCOL + col + j) * CSS];
        sc[j] = fmaxf(1.0f - SHRK / (sqrtf(cs) + EPSI), 0.0f);
    }

    float c8[8] = {0.f, 0.f, 0.f, 0.f, 0.f, 0.f, 0.f, 0.f};
    uint4 pu, ph;
    {
        const int p0 = rev ? (NPAIR - 1 - blockIdx.x) : blockIdx.x;
        const size_t b = ((size_t)(p0 * 2 + half)) * NCOL + col;
        pu = *(const uint4*)(g_u + b);
        ph = *(const uint4*)(g_h + b);
    }

    int it = 0;
    for (int w = blockIdx.x; w < NPAIR; w += GRID, ++it) {
        const int cur  = it & 1;
        const int pair = rev ? (NPAIR - 1 - w) : w;
        const size_t base = ((size_t)(pair * 2 + half)) * NCOL + col;

        float uu[8], hh[8];
        cvt8(pu, uu);
        cvt8(ph, hh);

        float e[8], zp[8];
#pragma unroll
        for (int j = 0; j < 8; ++j) {
            float s  = fmaxf(uu[j] - THR, 0.0f);    /* u > 0 always */
            float X  = sc[j] * s;
            zp[j]    = uu[j] - X;                   /* Z_k > 0 */
            float sx = sqrtf(X) + SQMIN;            /* branchless MIN_VALUE path */
            e[j]     = hh[j] * sx * ex2(K2E * zp[j]);
        }
        float local = ((e[0] + e[1]) + (e[2] + e[3])) + ((e[4] + e[5]) + (e[6] + e[7]));
        local = wredsum(local);
        if (lane == 0) sp[cur][half][wir] = local;

        int nw = w + GRID; if (nw >= NPAIR) nw = w;  /* safe redundant prefetch */
        {
            const int np = rev ? (NPAIR - 1 - nw) : nw;
            const size_t nb = ((size_t)(np * 2 + half)) * NCOL + col;
            pu = *(const uint4*)(g_u + nb);
            ph = *(const uint4*)(g_h + nb);
        }
        __syncthreads();
        const float S = (sp[cur][half][0] + sp[cur][half][1]) +
                        (sp[cur][half][2] + sp[cur][half][3]);
        const float inv = __fdividef(1.0f, S);

        if (last) {
            float4 o0, o1;
            o0.x = e[0] * inv; o0.y = e[1] * inv; o0.z = e[2] * inv; o0.w = e[3] * inv;
            o1.x = e[4] * inv; o1.y = e[5] * inv; o1.z = e[6] * inv; o1.w = e[7] * inv;
            *(float4*)(out + base)     = o0;
            *(float4*)(out + base + 4) = o1;
        } else {
            float un[8];
#pragma unroll
            for (int j = 0; j < 8; ++j) {
                un[j] = e[j] * inv + zp[j];          /* u_{k+1} = R_{k+1} + Z_k */
                float s2 = fmaxf(un[j] - THR, 0.0f);
                c8[j] += s2 * s2;
            }
            st8h(g_u + base, un);
        }
    }
    if (!last) {
#pragma unroll
        for (int j = 0; j < 8; ++j)
            atomicAdd(&g_cs[((size_t)(k + 1) * NCOL + col + j) * CSS], c8[j]);
    }
}

extern "C" void kernel_launch(void* const* d_in, const int* in_sizes, int n_in,
                              void* d_out, int out_size) {
    const float* r0 = (const float*)d_in[0];
    float* out = (float*)d_out;

    k_zero<<<NIT, NCOL>>>();
    k_init<<<GRID, NTHR>>>(r0);
    for (int k = 1; k < NIT; ++k)
        k_step<<<GRID, NTHR>>>(out, k, k & 1, (k == NIT - 1) ? 1 : 0);
}

// round 9
// speedup vs baseline: 1.0382x; 1.0382x over previous
#include <cuda_runtime.h>
#include <cuda_fp16.h>

#define NROWS 16384
#define NCOL  1024
#define NPAIR (NROWS / 2)     /* 8192 row pairs */
#define NTHR  256
#define NWARP (NTHR / 32)
#define GRID  592             /* 148 SMs x 4 CTAs, persistent */
#define NIT   20
#define CSS   64              /* colsum counter stride in floats (256 B) */
#define THR   0.05f           /* ALPHA*LAMBD/RHO */
#define SHRK  0.05f           /* (1-ALPHA)*LAMBD */
#define EPSI  1e-10f
#define SQMIN 1e-20f          /* sqrt(MIN_VALUE) */
#define K2E   (-0.72134752044448170f)  /* -0.5 * log2(e) */

__device__ __half g_u[NROWS * NCOL];                 /* fp16 u_k = R_k + Z_{k-1}; u > 0 */
__device__ __half g_h[NROWS * NCOL];                 /* fp16 sqrt(R_0c) */
__device__ float  g_cs[(size_t)NIT * NCOL * CSS];

__global__ void k_zero() {
    g_cs[((size_t)blockIdx.x * NCOL + threadIdx.x) * CSS] = 0.0f;
}

__device__ __forceinline__ float ex2(float x) {
    float r;
    asm("ex2.approx.f32 %0, %1;" : "=f"(r) : "f"(x));
    return r;
}

__device__ __forceinline__ float wredsum(float v) {
#pragma unroll
    for (int o = 16; o > 0; o >>= 1) v += __shfl_xor_sync(0xffffffffu, v, o);
    return v;
}

__device__ __forceinline__ void cvt4(const uint2 pk, float f[4]) {
    __half2 a = *reinterpret_cast<const __half2*>(&pk.x);
    __half2 b = *reinterpret_cast<const __half2*>(&pk.y);
    float2 fa = __half22float2(a), fb = __half22float2(b);
    f[0] = fa.x; f[1] = fa.y; f[2] = fb.x; f[3] = fb.y;
}

__device__ __forceinline__ void st4h(__half* p, const float f[4]) {
    __half2 a = __floats2half2_rn(f[0], f[1]);
    __half2 b = __floats2half2_rn(f[2], f[3]);
    uint2 pk;
    pk.x = *reinterpret_cast<unsigned*>(&a);
    pk.y = *reinterpret_cast<unsigned*>(&b);
    *(uint2*)p = pk;
}

/* sum 8 warp partials via two float4 smem loads */
__device__ __forceinline__ float sum8(const float* sp) {
    float4 a = *(const float4*)sp;
    float4 b = *(const float4*)(sp + 4);
    return ((a.x + a.y) + (a.z + a.w)) + ((b.x + b.y) + (b.z + b.w));
}

// u_1 = R_1 = R_0c / rowsum(R_0c)  (Z_0 = 0); writes fp16 u_1, fp16 sqrt(R_0c); colsum_1.
__global__ void __launch_bounds__(NTHR, 4) k_init(const float* __restrict__ r0) {
    __shared__ __align__(16) float sp[2][2][NWARP];
    const int tid  = threadIdx.x;
    const int lane = tid & 31;
    const int wid  = tid >> 5;
    const int col  = tid * 4;

    float c4[4] = {0.f, 0.f, 0.f, 0.f};

    float4 a0, a1;
    {
        const size_t b = (size_t)blockIdx.x * 2 * NCOL + col;
        a0 = *(const float4*)(r0 + b);
        a1 = *(const float4*)(r0 + b + NCOL);
    }

    int it = 0;
    for (int w = blockIdx.x; w < NPAIR; w += GRID, ++it) {
        const int cur = it & 1;
        float v0[4] = {a0.x, a0.y, a0.z, a0.w};
        float v1[4] = {a1.x, a1.y, a1.z, a1.w};
#pragma unroll
        for (int j = 0; j < 4; ++j) {
            if (v0[j] == 0.0f) v0[j] = 1e-40f;
            if (v1[j] == 0.0f) v1[j] = 1e-40f;
        }
        float p0 = wredsum((v0[0] + v0[1]) + (v0[2] + v0[3]));
        float p1 = wredsum((v1[0] + v1[1]) + (v1[2] + v1[3]));
        if (lane == 0) { sp[cur][0][wid] = p0; sp[cur][1][wid] = p1; }

        int nw = w + GRID; if (nw >= NPAIR) nw = w;     /* safe redundant prefetch */
        {
            const size_t nb = (size_t)nw * 2 * NCOL + col;
            a0 = *(const float4*)(r0 + nb);
            a1 = *(const float4*)(r0 + nb + NCOL);
        }
        __syncthreads();
        const float i0 = __fdividef(1.0f, sum8(sp[cur][0]));
        const float i1 = __fdividef(1.0f, sum8(sp[cur][1]));

        const size_t base = (size_t)w * 2 * NCOL + col;
        float r0n[4], r1n[4], q0[4], q1[4];
#pragma unroll
        for (int j = 0; j < 4; ++j) {
            r0n[j] = v0[j] * i0;  r1n[j] = v1[j] * i1;
            q0[j]  = sqrtf(v0[j]); q1[j] = sqrtf(v1[j]);
        }
        st4h(g_u + base,        r0n);
        st4h(g_u + base + NCOL, r1n);
        st4h(g_h + base,        q0);
        st4h(g_h + base + NCOL, q1);
#pragma unroll
        for (int j = 0; j < 4; ++j) {
            float s0 = fmaxf(r0n[j] - THR, 0.0f);
            float s1 = fmaxf(r1n[j] - THR, 0.0f);
            c4[j] += s0 * s0 + s1 * s1;
        }
    }
#pragma unroll
    for (int j = 0; j < 4; ++j)
        atomicAdd(&g_cs[((size_t)1 * NCOL + col + j) * CSS], c4[j]);
}

// Step k: u_k -> u_{k+1}, colsum_{k+1}; last step writes fp32 R_20 to out.
// e = sqrt(r0c) * (sqrt(X) + 1e-20) * exp2(K2E * z)   [branchless MIN_VALUE path]
__global__ void __launch_bounds__(NTHR, 4) k_step(float* __restrict__ out,
                                                  int k, int rev, int last) {
    __shared__ __align__(16) float sp[2][2][NWARP];
    const int tid  = threadIdx.x;
    const int lane = tid & 31;
    const int wid  = tid >> 5;
    const int col  = tid * 4;

    float sc[4];
#pragma unroll
    for (int j = 0; j < 4; ++j) {
        float cs = g_cs[((size_t)k * NCOL + col + j) * CSS];
        sc[j] = fmaxf(1.0f - SHRK / (sqrtf(cs) + EPSI), 0.0f);
    }

    float c4[4] = {0.f, 0.f, 0.f, 0.f};
    uint2 pu0, pu1, ph0, ph1;                           /* raw fp16 prefetch regs */
    {
        const int p0 = rev ? (NPAIR - 1 - blockIdx.x) : blockIdx.x;
        const size_t b = (size_t)p0 * 2 * NCOL + col;
        pu0 = *(const uint2*)(g_u + b); pu1 = *(const uint2*)(g_u + b + NCOL);
        ph0 = *(const uint2*)(g_h + b); ph1 = *(const uint2*)(g_h + b + NCOL);
    }

    int it = 0;
    for (int w = blockIdx.x; w < NPAIR; w += GRID, ++it) {
        const int cur  = it & 1;
        const int pair = rev ? (NPAIR - 1 - w) : w;
        const size_t base = (size_t)pair * 2 * NCOL + col;

        float uu0[4], uu1[4], hh0[4], hh1[4];
        cvt4(pu0, uu0); cvt4(pu1, uu1);
        cvt4(ph0, hh0); cvt4(ph1, hh1);

        float e0[4], e1[4], zp0[4], zp1[4];
#pragma unroll
        for (int j = 0; j < 4; ++j) {
            float s  = fmaxf(uu0[j] - THR, 0.0f);   /* u > 0 always */
            float X  = sc[j] * s;
            zp0[j]   = uu0[j] - X;                  /* Z_k */
            float sx = sqrtf(X) + SQMIN;
            e0[j]    = hh0[j] * sx * ex2(K2E * zp0[j]);
        }
#pragma unroll
        for (int j = 0; j < 4; ++j) {
            float s  = fmaxf(uu1[j] - THR, 0.0f);
            float X  = sc[j] * s;
            zp1[j]   = uu1[j] - X;
            float sx = sqrtf(X) + SQMIN;
            e1[j]    = hh1[j] * sx * ex2(K2E * zp1[j]);
        }
        float p0 = wredsum((e0[0] + e0[1]) + (e0[2] + e0[3]));
        float p1 = wredsum((e1[0] + e1[1]) + (e1[2] + e1[3]));
        if (lane == 0) { sp[cur][0][wid] = p0; sp[cur][1][wid] = p1; }

        int nw = w + GRID; if (nw >= NPAIR) nw = w;  /* safe redundant prefetch */
        {
            const int np = rev ? (NPAIR - 1 - nw) : nw;
            const size_t nb = (size_t)np * 2 * NCOL + col;
            pu0 = *(const uint2*)(g_u + nb); pu1 = *(const uint2*)(g_u + nb + NCOL);
            ph0 = *(const uint2*)(g_h + nb); ph1 = *(const uint2*)(g_h + nb + NCOL);
        }
        __syncthreads();
        const float i0 = __fdividef(1.0f, sum8(sp[cur][0]));
        const float i1 = __fdividef(1.0f, sum8(sp[cur][1]));

        if (last) {
            float4 o0, o1;
            o0.x = e0[0] * i0; o0.y = e0[1] * i0; o0.z = e0[2] * i0; o0.w = e0[3] * i0;
            o1.x = e1[0] * i1; o1.y = e1[1] * i1; o1.z = e1[2] * i1; o1.w = e1[3] * i1;
            *(float4*)(out + base)        = o0;
            *(float4*)(out + base + NCOL) = o1;
        } else {
            float un0[4], un1[4];
#pragma unroll
            for (int j = 0; j < 4; ++j) {
                un0[j] = e0[j] * i0 + zp0[j];        /* u_{k+1} = R_{k+1} + Z_k */
                un1[j] = e1[j] * i1 + zp1[j];
                float s0 = fmaxf(un0[j] - THR, 0.0f);
                float s1 = fmaxf(un1[j] - THR, 0.0f);
                c4[j] += s0 * s0 + s1 * s1;
            }
            st4h(g_u + base,        un0);
            st4h(g_u + base + NCOL, un1);
        }
    }
    if (!last) {
#pragma unroll
        for (int j = 0; j < 4; ++j)
            atomicAdd(&g_cs[((size_t)(k + 1) * NCOL + col + j) * CSS], c4[j]);
    }
}

extern "C" void kernel_launch(void* const* d_in, const int* in_sizes, int n_in,
                              void* d_out, int out_size) {
    const float* r0 = (const float*)d_in[0];
    float* out = (float*)d_out;

    k_zero<<<NIT, NCOL>>>();
    k_init<<<GRID, NTHR>>>(r0);
    for (int k = 1; k < NIT; ++k)
        k_step<<<GRID, NTHR>>>(out, k, k & 1, (k == NIT - 1) ? 1 : 0);
}

// round 10
// speedup vs baseline: 1.2847x; 1.2375x over previous
#include <cuda_runtime.h>
#include <cuda_fp16.h>

#define NROWS 16384
#define NCOL  1024
#define NPAIR (NROWS / 2)     /* 8192 row pairs */
#define NTHR  256
#define NWARP (NTHR / 32)
#define GRID  592             /* 148 SMs x 4 CTAs, persistent */
#define NIT   20
#define CSS   64              /* colsum counter stride in floats (256 B) */
#define THR   0.05f           /* ALPHA*LAMBD/RHO */
#define SHRK  0.05f           /* (1-ALPHA)*LAMBD */
#define EPSI  1e-10f
#define SQMIN 1e-20f          /* sqrt(MIN_VALUE) */

__device__ __half g_u[NROWS * NCOL];                 /* fp16 u_k = R_k + Z_{k-1} */
__device__ __half g_h[NROWS * NCOL];                 /* fp16 sqrt(R_0c) */
__device__ float  g_cs[(size_t)NIT * NCOL * CSS];

__global__ void k_zero() {
    g_cs[((size_t)blockIdx.x * NCOL + threadIdx.x) * CSS] = 0.0f;
}

/* single-MUFU sqrt; sqrt.approx.f32(0) == 0 exactly (PTX ISA) */
__device__ __forceinline__ float sqrt_ap(float x) {
    float r;
    asm("sqrt.approx.f32 %0, %1;" : "=f"(r) : "f"(x));
    return r;
}

/* soft threshold as x - clamp(x, -THR, THR): 3 ops, exact */
__device__ __forceinline__ float soft(float x) {
    return x - fminf(fmaxf(x, -THR), THR);
}

__device__ __forceinline__ float wredsum(float v) {
#pragma unroll
    for (int o = 16; o > 0; o >>= 1) v += __shfl_xor_sync(0xffffffffu, v, o);
    return v;
}

__device__ __forceinline__ void ld4h(const __half* p, float f[4]) {
    uint2 pk = *(const uint2*)p;
    __half2 a = *reinterpret_cast<__half2*>(&pk.x);
    __half2 b = *reinterpret_cast<__half2*>(&pk.y);
    float2 fa = __half22float2(a), fb = __half22float2(b);
    f[0] = fa.x; f[1] = fa.y; f[2] = fb.x; f[3] = fb.y;
}

__device__ __forceinline__ void st4h(__half* p, const float f[4]) {
    __half2 a = __floats2half2_rn(f[0], f[1]);
    __half2 b = __floats2half2_rn(f[2], f[3]);
    uint2 pk;
    pk.x = *reinterpret_cast<unsigned*>(&a);
    pk.y = *reinterpret_cast<unsigned*>(&b);
    *(uint2*)p = pk;
}

// u_1 = R_1 = R_0c / rowsum(R_0c)  (Z_0 = 0); writes fp16 u_1, fp16 sqrt(R_0c); colsum_1.
__global__ void __launch_bounds__(NTHR, 4) k_init(const float* __restrict__ r0) {
    __shared__ float sp[2][2][NWARP];
    const int tid  = threadIdx.x;
    const int lane = tid & 31;
    const int wid  = tid >> 5;
    const int col  = tid * 4;

    float c4[4] = {0.f, 0.f, 0.f, 0.f};

    float4 a0, a1, na0, na1;
    {
        const size_t b = (size_t)blockIdx.x * 2 * NCOL + col;
        a0 = *(const float4*)(r0 + b);
        a1 = *(const float4*)(r0 + b + NCOL);
    }

    int it = 0;
    for (int pair = blockIdx.x; pair < NPAIR; pair += GRID, ++it) {
        const int cur = it & 1;
        float v0[4] = {a0.x, a0.y, a0.z, a0.w};
        float v1[4] = {a1.x, a1.y, a1.z, a1.w};
#pragma unroll
        for (int j = 0; j < 4; ++j) {
            if (v0[j] == 0.0f) v0[j] = 1e-40f;
            if (v1[j] == 0.0f) v1[j] = 1e-40f;
        }
        float p0 = wredsum((v0[0] + v0[1]) + (v0[2] + v0[3]));
        float p1 = wredsum((v1[0] + v1[1]) + (v1[2] + v1[3]));
        if (lane == 0) { sp[cur][0][wid] = p0; sp[cur][1][wid] = p1; }

        int np = pair + GRID; if (np >= NPAIR) np = pair;   // safe redundant prefetch
        {
            const size_t nb = (size_t)np * 2 * NCOL + col;
            na0 = *(const float4*)(r0 + nb);
            na1 = *(const float4*)(r0 + nb + NCOL);
        }
        __syncthreads();
        float S0 = 0.f, S1 = 0.f;
#pragma unroll
        for (int w = 0; w < NWARP; ++w) { S0 += sp[cur][0][w]; S1 += sp[cur][1][w]; }
        const float i0 = __fdividef(1.0f, S0);
        const float i1 = __fdividef(1.0f, S1);

        const size_t base = (size_t)pair * 2 * NCOL + col;
        float r0n[4], r1n[4], q0[4], q1[4];
#pragma unroll
        for (int j = 0; j < 4; ++j) {
            r0n[j] = v0[j] * i0;     r1n[j] = v1[j] * i1;
            q0[j]  = sqrt_ap(v0[j]); q1[j] = sqrt_ap(v1[j]);
        }
        st4h(g_u + base,        r0n);
        st4h(g_u + base + NCOL, r1n);
        st4h(g_h + base,        q0);
        st4h(g_h + base + NCOL, q1);
#pragma unroll
        for (int j = 0; j < 4; ++j) {
            float s0 = soft(r0n[j]), s1 = soft(r1n[j]);
            c4[j] += s0 * s0 + s1 * s1;
        }
        a0 = na0; a1 = na1;
    }
#pragma unroll
    for (int j = 0; j < 4; ++j)
        atomicAdd(&g_cs[((size_t)1 * NCOL + col + j) * CSS], c4[j]);
}

// Step k: u_k -> u_{k+1}, colsum_{k+1}; last step writes fp32 R_20 to out.
// e = sqrt(r0c) * (sqrt_ap(X) + 1e-20) * exp(-z/2)
//   (X==0 -> exactly the reference MIN_VALUE branch since sqrt.approx(0)=0)
__global__ void __launch_bounds__(NTHR, 4) k_step(float* __restrict__ out,
                                                  int k, int rev, int last) {
    __shared__ float sp[2][2][NWARP];
    const int tid  = threadIdx.x;
    const int lane = tid & 31;
    const int wid  = tid >> 5;
    const int col  = tid * 4;

    float sc[4];
#pragma unroll
    for (int j = 0; j < 4; ++j) {
        float cs = g_cs[((size_t)k * NCOL + col + j) * CSS];
        sc[j] = fmaxf(1.0f - SHRK / (sqrtf(cs) + EPSI), 0.0f);
    }

    float c4[4] = {0.f, 0.f, 0.f, 0.f};
    float uu0[4], uu1[4], hh0[4], hh1[4];
    float nu0[4], nu1[4], nh0[4], nh1[4];

    int pair0 = rev ? (NPAIR - 1 - blockIdx.x) : blockIdx.x;
    {
        const size_t b = (size_t)pair0 * 2 * NCOL + col;
        ld4h(g_u + b, uu0);  ld4h(g_u + b + NCOL, uu1);
        ld4h(g_h + b, hh0);  ld4h(g_h + b + NCOL, hh1);
    }

    int it = 0;
    for (int w = blockIdx.x; w < NPAIR; w += GRID, ++it) {
        const int cur  = it & 1;
        const int pair = rev ? (NPAIR - 1 - w) : w;

        float e0[4], e1[4], zp0[4], zp1[4];
#pragma unroll
        for (int j = 0; j < 4; ++j) {
            float s  = soft(uu0[j]);
            float X  = sc[j] * s;
            zp0[j]   = uu0[j] - X;                          // Z_k
            float sx = sqrt_ap(X) + SQMIN;                  // branchless MIN_VALUE path
            e0[j]    = hh0[j] * sx * __expf(-0.5f * zp0[j]);
        }
#pragma unroll
        for (int j = 0; j < 4; ++j) {
            float s  = soft(uu1[j]);
            float X  = sc[j] * s;
            zp1[j]   = uu1[j] - X;
            float sx = sqrt_ap(X) + SQMIN;
            e1[j]    = hh1[j] * sx * __expf(-0.5f * zp1[j]);
        }
        float p0 = wredsum((e0[0] + e0[1]) + (e0[2] + e0[3]));
        float p1 = wredsum((e1[0] + e1[1]) + (e1[2] + e1[3]));
        if (lane == 0) { sp[cur][0][wid] = p0; sp[cur][1][wid] = p1; }

        int nw = w + GRID; if (nw >= NPAIR) nw = w;          // safe redundant prefetch
        {
            const int npair = rev ? (NPAIR - 1 - nw) : nw;
            const size_t nb = (size_t)npair * 2 * NCOL + col;
            ld4h(g_u + nb, nu0);  ld4h(g_u + nb + NCOL, nu1);
            ld4h(g_h + nb, nh0);  ld4h(g_h + nb + NCOL, nh1);
        }
        __syncthreads();
        float S0 = 0.f, S1 = 0.f;
#pragma unroll
        for (int ww = 0; ww < NWARP; ++ww) { S0 += sp[cur][0][ww]; S1 += sp[cur][1][ww]; }
        const float i0 = __fdividef(1.0f, S0);
        const float i1 = __fdividef(1.0f, S1);

        const size_t base = (size_t)pair * 2 * NCOL + col;
        float rn0[4], rn1[4];
#pragma unroll
        for (int j = 0; j < 4; ++j) { rn0[j] = e0[j] * i0; rn1[j] = e1[j] * i1; }

        if (last) {
            *(float4*)(out + base)        = make_float4(rn0[0], rn0[1], rn0[2], rn0[3]);
            *(float4*)(out + base + NCOL) = make_float4(rn1[0], rn1[1], rn1[2], rn1[3]);
        } else {
            float un0[4], un1[4];
#pragma unroll
            for (int j = 0; j < 4; ++j) {
                un0[j] = rn0[j] + zp0[j];                   // u_{k+1}
                un1[j] = rn1[j] + zp1[j];
                float s0 = soft(un0[j]), s1 = soft(un1[j]);
                c4[j] += s0 * s0 + s1 * s1;
            }
            st4h(g_u + base,        un0);
            st4h(g_u + base + NCOL, un1);
        }
#pragma unroll
        for (int j = 0; j < 4; ++j) {
            uu0[j] = nu0[j]; uu1[j] = nu1[j];
            hh0[j] = nh0[j]; hh1[j] = nh1[j];
        }
    }
    if (!last) {
#pragma unroll
        for (int j = 0; j < 4; ++j)
            atomicAdd(&g_cs[((size_t)(k + 1) * NCOL + col + j) * CSS], c4[j]);
    }
}

extern "C" void kernel_launch(void* const* d_in, const int* in_sizes, int n_in,
                              void* d_out, int out_size) {
    const float* r0 = (const float*)d_in[0];
    float* out = (float*)d_out;

    k_zero<<<NIT, NCOL>>>();
    k_init<<<GRID, NTHR>>>(r0);
    for (int k = 1; k < NIT; ++k)
        k_step<<<GRID, NTHR>>>(out, k, k & 1, (k == NIT - 1) ? 1 : 0);
}